// round 4
// baseline (speedup 1.0000x reference)
#include <cuda_runtime.h>

#define N_NODES 100000
#define D 128

// Scratch (no cudaMalloc allowed).
__device__ int g_deg[3 * N_NODES];
__device__ int g_is64;   // 1 if edge indices are int64, 0 if int32

// Detect edge-index dtype on-device: int32 data read as int64 fuses index
// pairs into values >= 2^32 (unless the high word happens to be 0, P~1e-5
// per entry). 128 entries -> misdetection probability ~1e-640.
__global__ void detect_kernel(const void* ei) {
    if (blockIdx.x == 0 && threadIdx.x == 0) {
        const long long* p = (const long long*)ei;
        int ok64 = 1;
        for (int i = 0; i < 128; i++) {
            long long v = p[i];
            if (v < 0 || v >= N_NODES) { ok64 = 0; break; }
        }
        g_is64 = ok64;
    }
}

__device__ __forceinline__ int load_idx(const void* ei, long long pos, int is64) {
    int v = is64 ? (int)((const long long*)ei)[pos] : ((const int*)ei)[pos];
    // clamp: turns any residual dtype misread into a rel_err signal, not a trap
    return (v < 0) ? 0 : (v >= N_NODES ? N_NODES - 1 : v);
}

__global__ void zero_deg_kernel() {
    int i = blockIdx.x * blockDim.x + threadIdx.x;
    if (i < 3 * N_NODES) g_deg[i] = 0;
}

template <int S>
__global__ void deg_kernel(const void* __restrict__ ei, int n_edges, int rel) {
    int e = blockIdx.x * blockDim.x + threadIdx.x;
    if (e < n_edges) {
        int is64 = g_is64;
        // row 1 starts at offset n_edges*S; dest of hyperedge e = first entry of its group
        int dest = load_idx(ei, (long long)n_edges * S + (long long)e * S, is64);
        atomicAdd(&g_deg[rel * N_NODES + dest], 1);
    }
}

// out[i][:] = x[i][:] @ C_w + C_b    (64-row tile, 256 threads, K chunked by 32)
__global__ __launch_bounds__(256) void base_kernel(
    const float* __restrict__ x, const float* __restrict__ Cw,
    const float* __restrict__ Cb, float* __restrict__ out, int n_nodes) {
    __shared__ float A_s[32][128];
    __shared__ float X_s[64][33];
    __shared__ float b_s[128];
    int t = threadIdx.x;
    int w = t >> 5, tn = t & 31;
    int row0 = blockIdx.x * 64;
    if (t < 128) b_s[t] = Cb[t];

    float acc[8][4];
#pragma unroll
    for (int m = 0; m < 8; m++)
#pragma unroll
        for (int j = 0; j < 4; j++) acc[m][j] = 0.f;

    for (int kc = 0; kc < 4; kc++) {
        __syncthreads();
#pragma unroll
        for (int i = 0; i < 4; i++) {                 // A chunk: 32x128 floats as float4
            int l = t + 256 * i;
            int r = l >> 5, c = l & 31;
            ((float4*)A_s[r])[c] = ((const float4*)(Cw + (long long)(kc * 32 + r) * 128))[c];
        }
#pragma unroll
        for (int i = 0; i < 8; i++) {                 // X chunk: 64x32 floats
            int l = t + 256 * i;
            int r = l >> 5, c = l & 31;
            int row = row0 + r;
            float v = 0.f;
            if (row < n_nodes) v = x[(long long)row * 128 + kc * 32 + c];
            X_s[r][c] = v;
        }
        __syncthreads();
#pragma unroll
        for (int k = 0; k < 32; k++) {
            float4 a = ((float4*)A_s[k])[tn];
#pragma unroll
            for (int m = 0; m < 8; m++) {
                float g = X_s[w * 8 + m][k];
                acc[m][0] += g * a.x;
                acc[m][1] += g * a.y;
                acc[m][2] += g * a.z;
                acc[m][3] += g * a.w;
            }
        }
    }
#pragma unroll
    for (int m = 0; m < 8; m++) {
        int row = row0 + w * 8 + m;
        if (row < n_nodes) {
            float4 v;
            v.x = acc[m][0] + b_s[tn * 4 + 0];
            v.y = acc[m][1] + b_s[tn * 4 + 1];
            v.z = acc[m][2] + b_s[tn * 4 + 2];
            v.w = acc[m][3] + b_s[tn * 4 + 3];
            ((float4*)(out + (long long)row * 128))[tn] = v;
        }
    }
}

// Hyperedge GEMM + normalized scatter-add.
// Tile: 64 hyperedges x 128 outputs, K = S*128 chunked by 32.
template <int S>
__global__ __launch_bounds__(256) void msg_kernel(
    const float* __restrict__ x, const void* __restrict__ ei,
    const float* __restrict__ A, float* __restrict__ out,
    int n_edges, int rel) {
    __shared__ float A_s[32][128];
    __shared__ float G_s[64][33];
    __shared__ int s_src[64][3];
    __shared__ int s_dest[64];
    __shared__ float s_inv[64];

    int t = threadIdx.x;
    int w = t >> 5, tn = t & 31;
    int e0 = blockIdx.x * 64;
    int m_count = n_edges - e0;
    if (m_count > 64) m_count = 64;
    int is64 = g_is64;

    // Load per-tile edge metadata
    for (int l = t; l < 64 * S; l += 256) {
        int e = l / S, k = l - e * S;
        int src = 0;
        if (e < m_count) src = load_idx(ei, (long long)(e0 + e) * S + k, is64);
        s_src[e][k] = src;
    }
    if (t < 64) {
        if (t < m_count) {
            int dst = load_idx(ei, (long long)n_edges * S + (long long)(e0 + t) * S, is64);
            s_dest[t] = dst;
            int dg = g_deg[rel * N_NODES + dst];
            s_inv[t] = 1.0f / (float)(dg > 0 ? dg : 1);
        }
    }

    float acc[8][4];
#pragma unroll
    for (int m = 0; m < 8; m++)
#pragma unroll
        for (int j = 0; j < 4; j++) acc[m][j] = 0.f;

    const int NK = 4 * S;  // number of 32-wide K chunks
#pragma unroll 1
    for (int kc = 0; kc < NK; kc++) {
        __syncthreads();
#pragma unroll
        for (int i = 0; i < 4; i++) {                 // A chunk
            int l = t + 256 * i;
            int r = l >> 5, c = l & 31;
            ((float4*)A_s[r])[c] = ((const float4*)(A + (long long)(kc * 32 + r) * 128))[c];
        }
        int ks = (kc * 32) >> 7;    // which source slot within the hyperedge
        int cb = (kc * 32) & 127;   // column base within that source's feature row
#pragma unroll
        for (int i = 0; i < 8; i++) {                 // gathered chunk: 64x32
            int l = t + 256 * i;
            int r = l >> 5, c = l & 31;
            int src = s_src[r][ks];
            G_s[r][c] = x[(long long)src * 128 + cb + c];
        }
        __syncthreads();
#pragma unroll
        for (int k = 0; k < 32; k++) {
            float4 a = ((float4*)A_s[k])[tn];
#pragma unroll
            for (int m = 0; m < 8; m++) {
                float g = G_s[w * 8 + m][k];
                acc[m][0] += g * a.x;
                acc[m][1] += g * a.y;
                acc[m][2] += g * a.z;
                acc[m][3] += g * a.w;
            }
        }
    }

    // Normalize by in-degree and scatter-add (scalar RED.E.ADD.F32 — no return)
#pragma unroll
    for (int m = 0; m < 8; m++) {
        int el = w * 8 + m;
        if (el < m_count) {
            float inv = s_inv[el];
            int dst = s_dest[el];
            float* addr = out + (long long)dst * 128 + tn * 4;
            atomicAdd(addr + 0, acc[m][0] * inv);
            atomicAdd(addr + 1, acc[m][1] * inv);
            atomicAdd(addr + 2, acc[m][2] * inv);
            atomicAdd(addr + 3, acc[m][3] * inv);
        }
    }
}

extern "C" void kernel_launch(void* const* d_in, const int* in_sizes, int n_in,
                              void* d_out, int out_size) {
    // Identify inputs by element count (dtype-independent). Size collisions
    // (A_r1/C_w both 16384, ei_r2/ei_r3 both 1.2M) resolved by first-occurrence:
    // both plausible metadata orderings put A_r1 before C_w and ei_r2 before ei_r3.
    const float *x = nullptr, *A1 = nullptr, *A2 = nullptr, *A3 = nullptr;
    const float *Cw = nullptr, *Cb = nullptr;
    const void *e1 = nullptr, *e2 = nullptr, *e3 = nullptr;

    for (int i = 0; i < n_in; i++) {
        int sz = in_sizes[i];
        if (sz == 12800000)      x = (const float*)d_in[i];
        else if (sz == 16384) {  if (!A1) A1 = (const float*)d_in[i]; else Cw = (const float*)d_in[i]; }
        else if (sz == 32768)    A2 = (const float*)d_in[i];
        else if (sz == 49152)    A3 = (const float*)d_in[i];
        else if (sz == 128)      Cb = (const float*)d_in[i];
        else if (sz == 800000)   e1 = d_in[i];
        else if (sz == 1200000){ if (!e2) e2 = d_in[i]; else e3 = d_in[i]; }
    }

    float* out = (float*)d_out;
    const int n1 = 400000, n2 = 300000, n3 = 200000;

    // 0) detect edge-index dtype (int32 vs int64) on-device
    detect_kernel<<<1, 1>>>(e1);

    // 1) zero degree scratch
    zero_deg_kernel<<<(3 * N_NODES + 255) / 256, 256>>>();

    // 2) per-relation in-degree counts
    deg_kernel<1><<<(n1 + 255) / 256, 256>>>(e1, n1, 0);
    deg_kernel<2><<<(n2 + 255) / 256, 256>>>(e2, n2, 1);
    deg_kernel<3><<<(n3 + 255) / 256, 256>>>(e3, n3, 2);

    // 3) base: out = x @ C_w + C_b (fully initializes d_out)
    base_kernel<<<(N_NODES + 63) / 64, 256>>>(x, Cw, Cb, out, N_NODES);

    // 4) hyperedge message GEMMs + scatter
    msg_kernel<1><<<(n1 + 63) / 64, 256>>>(x, e1, A1, out, n1, 0);
    msg_kernel<2><<<(n2 + 63) / 64, 256>>>(x, e2, A2, out, n2, 1);
    msg_kernel<3><<<(n3 + 63) / 64, 256>>>(x, e3, A3, out, n3, 2);
}

// round 6
// speedup vs baseline: 1.3634x; 1.3634x over previous
#include <cuda_runtime.h>
#include <cstdint>

#define N_NODES 100000

// ---------------- device scratch (no cudaMalloc allowed) ----------------
__device__ int   g_deg[3 * N_NODES];
__device__ int   g_is64;
__device__ float g_xt[(size_t)N_NODES * 128];   // x, tf32-rounded, K-permuted per 32-block
__device__ float g_At1[128 * 128];              // A_r^T, tf32-rounded, K-permuted  [n][k']
__device__ float g_At2[128 * 256];
__device__ float g_At3[128 * 384];

// fragment-friendly permutation within each 32-wide K block:
// c = ((k&7)<<2) | (k>>3)  so lane fragment series (k, k+8, k+16, k+24) is contiguous
__device__ __host__ __forceinline__ int kperm(int kl) { return ((kl & 7) << 2) | (kl >> 3); }

__device__ __forceinline__ float cvt_rna_tf32(float v) {
    uint32_t r;
    asm("cvt.rna.tf32.f32 %0, %1;" : "=r"(r) : "f"(v));
    return __uint_as_float(r);
}

__device__ __forceinline__ void mma_tf32(float* c, float a0, float a1, float a2, float a3,
                                         float b0, float b1) {
    asm volatile(
        "mma.sync.aligned.m16n8k8.row.col.f32.tf32.tf32.f32 "
        "{%0,%1,%2,%3}, {%4,%5,%6,%7}, {%8,%9}, {%0,%1,%2,%3};"
        : "+f"(c[0]), "+f"(c[1]), "+f"(c[2]), "+f"(c[3])
        : "r"(__float_as_uint(a0)), "r"(__float_as_uint(a1)),
          "r"(__float_as_uint(a2)), "r"(__float_as_uint(a3)),
          "r"(__float_as_uint(b0)), "r"(__float_as_uint(b1)));
}

__device__ __forceinline__ void red4(float* p, float x, float y, float z, float w) {
    asm volatile(
        "{ .reg .u64 g; cvta.to.global.u64 g, %0; "
        "red.global.add.v4.f32 [g], {%1,%2,%3,%4}; }"
        :: "l"(p), "f"(x), "f"(y), "f"(z), "f"(w) : "memory");
}

#define C4(v, ks) ((ks) == 0 ? (v).x : (ks) == 1 ? (v).y : (ks) == 2 ? (v).z : (v).w)

// ---------------- dtype detection + degree ----------------
__global__ void detect_kernel(const void* ei) {
    if (blockIdx.x == 0 && threadIdx.x == 0) {
        const long long* p = (const long long*)ei;
        int ok64 = 1;
        for (int i = 0; i < 128; i++) {
            long long v = p[i];
            if (v < 0 || v >= N_NODES) { ok64 = 0; break; }
        }
        g_is64 = ok64;
    }
}
__device__ __forceinline__ int load_idx(const void* ei, long long pos, int is64) {
    int v = is64 ? (int)((const long long*)ei)[pos] : ((const int*)ei)[pos];
    return (v < 0) ? 0 : (v >= N_NODES ? N_NODES - 1 : v);
}
__global__ void zero_deg_kernel() {
    int i = blockIdx.x * blockDim.x + threadIdx.x;
    if (i < 3 * N_NODES) g_deg[i] = 0;
}
template <int S>
__global__ void deg_kernel(const void* __restrict__ ei, int n_edges, int rel) {
    int e = blockIdx.x * blockDim.x + threadIdx.x;
    if (e < n_edges) {
        int is64 = g_is64;
        int dest = load_idx(ei, (long long)n_edges * S + (long long)e * S, is64);
        atomicAdd(&g_deg[rel * N_NODES + dest], 1);
    }
}

// ---------------- tf32 preconversion (with K permutation) ----------------
__global__ void conv_x_kernel(const float* __restrict__ x) {
    int i = blockIdx.x * blockDim.x + threadIdx.x;
    if (i < N_NODES * 128) {
        int node = i >> 7, k = i & 127;
        g_xt[(size_t)node * 128 + (k & 96) + kperm(k & 31)] = cvt_rna_tf32(x[i]);
    }
}
template <int S>
__global__ void transpose_kernel(const float* __restrict__ A) {
    float* At = (S == 1) ? g_At1 : (S == 2) ? g_At2 : g_At3;
    const int Ktot = S * 128;
    int idx = blockIdx.x * blockDim.x + threadIdx.x;
    if (idx < 128 * Ktot) {
        int k = idx >> 7, n = idx & 127;               // coalesced read of A[k][n]
        At[(size_t)n * Ktot + (k & ~31) + kperm(k & 31)] = cvt_rna_tf32(A[idx]);
    }
}

// ---------------- base GEMM (SIMT fp32, exact): out = x@Cw + b ----------------
__global__ __launch_bounds__(256) void base_kernel(
    const float* __restrict__ x, const float* __restrict__ Cw,
    const float* __restrict__ Cb, float* __restrict__ out, int n_nodes) {
    __shared__ float A_s[32][128];
    __shared__ float X_s[64][33];
    __shared__ float b_s[128];
    int t = threadIdx.x;
    int w = t >> 5, tn = t & 31;
    int row0 = blockIdx.x * 64;
    if (t < 128) b_s[t] = Cb[t];

    float acc[8][4];
#pragma unroll
    for (int m = 0; m < 8; m++)
#pragma unroll
        for (int j = 0; j < 4; j++) acc[m][j] = 0.f;

    for (int kc = 0; kc < 4; kc++) {
        __syncthreads();
#pragma unroll
        for (int i = 0; i < 4; i++) {
            int l = t + 256 * i;
            int r = l >> 5, c = l & 31;
            ((float4*)A_s[r])[c] = ((const float4*)(Cw + (long long)(kc * 32 + r) * 128))[c];
        }
#pragma unroll
        for (int i = 0; i < 8; i++) {
            int l = t + 256 * i;
            int r = l >> 5, c = l & 31;
            int row = row0 + r;
            float v = 0.f;
            if (row < n_nodes) v = x[(long long)row * 128 + kc * 32 + c];
            X_s[r][c] = v;
        }
        __syncthreads();
#pragma unroll
        for (int k = 0; k < 32; k++) {
            float4 a = ((float4*)A_s[k])[tn];
#pragma unroll
            for (int m = 0; m < 8; m++) {
                float g = X_s[w * 8 + m][k];
                acc[m][0] += g * a.x;
                acc[m][1] += g * a.y;
                acc[m][2] += g * a.z;
                acc[m][3] += g * a.w;
            }
        }
    }
#pragma unroll
    for (int m = 0; m < 8; m++) {
        int row = row0 + w * 8 + m;
        if (row < n_nodes) {
            float4 v;
            v.x = acc[m][0] + b_s[tn * 4 + 0];
            v.y = acc[m][1] + b_s[tn * 4 + 1];
            v.z = acc[m][2] + b_s[tn * 4 + 2];
            v.w = acc[m][3] + b_s[tn * 4 + 3];
            ((float4*)(out + (long long)row * 128))[tn] = v;
        }
    }
}

// ---------------- mma.sync tf32 edge-message kernel ----------------
// D(m=outcol 0..127, n=edge 0..127) = sum_k At[m][k] * G[e][k]
// Tile: 128 edges x 128 outs; K = S*128 in chunks of 32.
template <int S>
__global__ __launch_bounds__(256) void msg_mma(
    const void* __restrict__ ei, float* __restrict__ out, int n_edges, int rel) {
    __shared__ __align__(16) char s_raw[36864];     // As(18432) + Gs(18432); reused as stage
    __shared__ int s_src[128 * S];
    __shared__ int s_dst[128];
    __shared__ float s_inv[128];
    float* As = (float*)s_raw;                       // [128 m][36] (32 cols + pad)
    float* Gs = (float*)(s_raw + 18432);             // [128 e][36]
    float* stage = (float*)s_raw;                    // [64 e][132]

    const float* xt = g_xt;
    const float* At = (S == 1) ? g_At1 : (S == 2) ? g_At2 : g_At3;
    const int Ktot = S * 128;

    int t = threadIdx.x, l = t & 31, w = t >> 5;
    int wm = w & 3, wn = w >> 2;
    int e0 = blockIdx.x * 128;
    int m_count = n_edges - e0;
    if (m_count > 128) m_count = 128;
    int is64 = g_is64;

    // per-tile edge metadata
    for (int idx = t; idx < 128 * S; idx += 256) {
        int e = idx / S, k = idx - e * S;
        int src = 0;
        if (e < m_count) src = load_idx(ei, (long long)(e0 + e) * S + k, is64);
        s_src[idx] = src;
    }
    if (t < 128) {
        int dst = 0; float inv = 0.f;
        if (t < m_count) {
            dst = load_idx(ei, (long long)n_edges * S + (long long)(e0 + t) * S, is64);
            int dg = g_deg[rel * N_NODES + dst];
            inv = 1.0f / (float)(dg > 0 ? dg : 1);
        }
        s_dst[t] = dst; s_inv[t] = inv;
    }

    float c[2][8][4];
#pragma unroll
    for (int am = 0; am < 2; am++)
#pragma unroll
        for (int bi = 0; bi < 8; bi++)
#pragma unroll
            for (int j = 0; j < 4; j++) c[am][bi][j] = 0.f;

    const int NKC = 4 * S;
#pragma unroll 1
    for (int kc = 0; kc < NKC; kc++) {
        __syncthreads();                // previous chunk's mma reads done
        int ks_slot = kc >> 2;          // which source slot of the hyperedge
        int cb = (kc & 3) * 32;         // 32-col block within that slot
#pragma unroll
        for (int i = 0; i < 4; i++) {   // stage As + Gs (128x32 each, float4)
            int idx = t + 256 * i;
            int r = idx >> 3, q = idx & 7;
            float4 av = *(const float4*)(At + (size_t)r * Ktot + kc * 32 + q * 4);
            *(float4*)(As + r * 36 + q * 4) = av;
            int src = s_src[r * S + ks_slot];
            float4 gv = *(const float4*)(xt + (size_t)src * 128 + cb + q * 4);
            *(float4*)(Gs + r * 36 + q * 4) = gv;
        }
        __syncthreads();

        int m0 = wm * 32, n0 = wn * 64;
        float4 aF[2][4];
#pragma unroll
        for (int am = 0; am < 2; am++) {
            int mr = m0 + am * 16 + (l >> 2);
            aF[am][0] = *(float4*)(As + mr * 36 + (l & 3) * 4);
            aF[am][1] = *(float4*)(As + (mr + 8) * 36 + (l & 3) * 4);
            aF[am][2] = *(float4*)(As + mr * 36 + ((l & 3) + 4) * 4);
            aF[am][3] = *(float4*)(As + (mr + 8) * 36 + ((l & 3) + 4) * 4);
        }
#pragma unroll
        for (int bg = 0; bg < 2; bg++) {
            float4 bF[4][2];
#pragma unroll
            for (int bn = 0; bn < 4; bn++) {
                int er = n0 + (bg * 4 + bn) * 8 + (l >> 2);
                bF[bn][0] = *(float4*)(Gs + er * 36 + (l & 3) * 4);
                bF[bn][1] = *(float4*)(Gs + er * 36 + ((l & 3) + 4) * 4);
            }
#pragma unroll
            for (int ks = 0; ks < 4; ks++) {
#pragma unroll
                for (int am = 0; am < 2; am++) {
#pragma unroll
                    for (int bn = 0; bn < 4; bn++) {
                        mma_tf32(c[am][bg * 4 + bn],
                                 C4(aF[am][0], ks), C4(aF[am][1], ks),
                                 C4(aF[am][2], ks), C4(aF[am][3], ks),
                                 C4(bF[bn][0], ks), C4(bF[bn][1], ks));
                    }
                }
            }
        }
    }

    // epilogue: stage [64 e][128 m] halves in smem, vector-RED into out
#pragma unroll 1
    for (int h = 0; h < 2; h++) {
        __syncthreads();
        if (wn == h) {
            int m0 = wm * 32;
#pragma unroll
            for (int am = 0; am < 2; am++)
#pragma unroll
                for (int bi = 0; bi < 8; bi++) {
                    int eloc = bi * 8 + 2 * (l & 3);
                    int m = m0 + am * 16 + (l >> 2);
                    stage[eloc * 132 + m]           = c[am][bi][0];
                    stage[(eloc + 1) * 132 + m]     = c[am][bi][1];
                    stage[eloc * 132 + m + 8]       = c[am][bi][2];
                    stage[(eloc + 1) * 132 + m + 8] = c[am][bi][3];
                }
        }
        __syncthreads();
#pragma unroll 1
        for (int i = 0; i < 8; i++) {
            int idx = t + 256 * i;
            int eloc = idx >> 5, c4 = idx & 31;
            int e = h * 64 + eloc;
            if (e < m_count) {
                float inv = s_inv[e];
                float4 v = *(float4*)(stage + eloc * 132 + c4 * 4);
                float* p = out + (size_t)s_dst[e] * 128 + c4 * 4;
                red4(p, v.x * inv, v.y * inv, v.z * inv, v.w * inv);
            }
        }
    }
}

// ---------------- launch ----------------
extern "C" void kernel_launch(void* const* d_in, const int* in_sizes, int n_in,
                              void* d_out, int out_size) {
    const float *x = nullptr, *A1 = nullptr, *A2 = nullptr, *A3 = nullptr;
    const float *Cw = nullptr, *Cb = nullptr;
    const void *e1 = nullptr, *e2 = nullptr, *e3 = nullptr;

    for (int i = 0; i < n_in; i++) {
        int sz = in_sizes[i];
        if (sz == 12800000)      x = (const float*)d_in[i];
        else if (sz == 16384) {  if (!A1) A1 = (const float*)d_in[i]; else Cw = (const float*)d_in[i]; }
        else if (sz == 32768)    A2 = (const float*)d_in[i];
        else if (sz == 49152)    A3 = (const float*)d_in[i];
        else if (sz == 128)      Cb = (const float*)d_in[i];
        else if (sz == 800000)   e1 = d_in[i];
        else if (sz == 1200000){ if (!e2) e2 = d_in[i]; else e3 = d_in[i]; }
    }

    float* out = (float*)d_out;
    const int n1 = 400000, n2 = 300000, n3 = 200000;

    detect_kernel<<<1, 1>>>(e1);
    zero_deg_kernel<<<(3 * N_NODES + 255) / 256, 256>>>();
    deg_kernel<1><<<(n1 + 255) / 256, 256>>>(e1, n1, 0);
    deg_kernel<2><<<(n2 + 255) / 256, 256>>>(e2, n2, 1);
    deg_kernel<3><<<(n3 + 255) / 256, 256>>>(e3, n3, 2);

    conv_x_kernel<<<(N_NODES * 128 + 255) / 256, 256>>>(x);
    transpose_kernel<1><<<(128 * 128 + 255) / 256, 256>>>(A1);
    transpose_kernel<2><<<(128 * 256 + 255) / 256, 256>>>(A2);
    transpose_kernel<3><<<(128 * 384 + 255) / 256, 256>>>(A3);

    base_kernel<<<(N_NODES + 63) / 64, 256>>>(x, Cw, Cb, out, N_NODES);

    msg_mma<1><<<(n1 + 127) / 128, 256>>>(e1, out, n1, 0);
    msg_mma<2><<<(n2 + 127) / 128, 256>>>(e2, out, n2, 1);
    msg_mma<3><<<(n3 + 127) / 128, 256>>>(e3, out, n3, 2);
}

// round 7
// speedup vs baseline: 3.3352x; 2.4462x over previous
#include <cuda_runtime.h>
#include <cuda_fp16.h>
#include <cstdint>

#define N_NODES 100000

// ---------------- device scratch (no cudaMalloc allowed) ----------------
__device__ int    g_deg[3 * N_NODES];
__device__ int    g_is64;
__device__ __half g_xh[(size_t)N_NODES * 128];   // x -> fp16, word-permuted per k16 group
__device__ __half g_Ah1[128 * 128];              // A_r^T -> fp16, [n][k'] permuted
__device__ __half g_Ah2[128 * 256];
__device__ __half g_Ah3[128 * 384];

// Half-index permutation inside each 16-half (k16) group:
// word w (pair of halves) -> position (w&3)*2 + (w>>2), so the two words a lane
// needs for its mma fragment (w=c and w=c+4) are adjacent -> one LDS.64.
__device__ __forceinline__ int hperm(int k) {     // k in [0,128)
    int w = k >> 1, g = w >> 3, wl = w & 7;
    int p = (wl & 3) * 2 + (wl >> 2);
    return g * 16 + p * 2 + (k & 1);
}

__device__ __forceinline__ void mma_f16(float* c, uint32_t a0, uint32_t a1,
                                        uint32_t a2, uint32_t a3,
                                        uint32_t b0, uint32_t b1) {
    asm volatile(
        "mma.sync.aligned.m16n8k16.row.col.f32.f16.f16.f32 "
        "{%0,%1,%2,%3}, {%4,%5,%6,%7}, {%8,%9}, {%0,%1,%2,%3};"
        : "+f"(c[0]), "+f"(c[1]), "+f"(c[2]), "+f"(c[3])
        : "r"(a0), "r"(a1), "r"(a2), "r"(a3), "r"(b0), "r"(b1));
}

__device__ __forceinline__ void red4(float* p, float x, float y, float z, float w) {
    asm volatile(
        "{ .reg .u64 g; cvta.to.global.u64 g, %0; "
        "red.global.add.v4.f32 [g], {%1,%2,%3,%4}; }"
        :: "l"(p), "f"(x), "f"(y), "f"(z), "f"(w) : "memory");
}

// ---------------- dtype detection + degree ----------------
__global__ void detect_kernel(const void* ei) {
    if (blockIdx.x == 0 && threadIdx.x == 0) {
        const long long* p = (const long long*)ei;
        int ok64 = 1;
        for (int i = 0; i < 128; i++) {
            long long v = p[i];
            if (v < 0 || v >= N_NODES) { ok64 = 0; break; }
        }
        g_is64 = ok64;
    }
}
__device__ __forceinline__ int load_idx(const void* ei, long long pos, int is64) {
    int v = is64 ? (int)((const long long*)ei)[pos] : ((const int*)ei)[pos];
    return (v < 0) ? 0 : (v >= N_NODES ? N_NODES - 1 : v);
}
__global__ void zero_deg_kernel() {
    int i = blockIdx.x * blockDim.x + threadIdx.x;
    if (i < 3 * N_NODES) g_deg[i] = 0;
}
template <int S>
__global__ void deg_kernel(const void* __restrict__ ei, int n_edges, int rel) {
    int e = blockIdx.x * blockDim.x + threadIdx.x;
    if (e < n_edges) {
        int is64 = g_is64;
        int dest = load_idx(ei, (long long)n_edges * S + (long long)e * S, is64);
        atomicAdd(&g_deg[rel * N_NODES + dest], 1);
    }
}

// ---------------- fp16 preconversion (with fragment permutation) ----------------
__global__ void conv_x_kernel(const float* __restrict__ x) {
    int i = blockIdx.x * blockDim.x + threadIdx.x;
    if (i < N_NODES * 128) {
        int node = i >> 7, k = i & 127;
        g_xh[(size_t)node * 128 + hperm(k)] = __float2half_rn(x[i]);
    }
}
template <int S>
__global__ void transpose_kernel(const float* __restrict__ A) {
    __half* Ah = (S == 1) ? g_Ah1 : (S == 2) ? g_Ah2 : g_Ah3;
    const int Ktot = S * 128;
    int idx = blockIdx.x * blockDim.x + threadIdx.x;
    if (idx < 128 * Ktot) {
        int k = idx >> 7, n = idx & 127;               // coalesced read of A[k][n]
        Ah[(size_t)n * Ktot + (k & ~127) + hperm(k & 127)] = __float2half_rn(A[idx]);
    }
}

// ---------------- base GEMM (SIMT fp32, exact): out = x@Cw + b ----------------
__global__ __launch_bounds__(256) void base_kernel(
    const float* __restrict__ x, const float* __restrict__ Cw,
    const float* __restrict__ Cb, float* __restrict__ out, int n_nodes) {
    __shared__ float A_s[32][128];
    __shared__ float X_s[64][33];
    __shared__ float b_s[128];
    int t = threadIdx.x;
    int w = t >> 5, tn = t & 31;
    int row0 = blockIdx.x * 64;
    if (t < 128) b_s[t] = Cb[t];

    float acc[8][4];
#pragma unroll
    for (int m = 0; m < 8; m++)
#pragma unroll
        for (int j = 0; j < 4; j++) acc[m][j] = 0.f;

    for (int kc = 0; kc < 4; kc++) {
        __syncthreads();
#pragma unroll
        for (int i = 0; i < 4; i++) {
            int l = t + 256 * i;
            int r = l >> 5, c = l & 31;
            ((float4*)A_s[r])[c] = ((const float4*)(Cw + (long long)(kc * 32 + r) * 128))[c];
        }
#pragma unroll
        for (int i = 0; i < 8; i++) {
            int l = t + 256 * i;
            int r = l >> 5, c = l & 31;
            int row = row0 + r;
            float v = 0.f;
            if (row < n_nodes) v = x[(long long)row * 128 + kc * 32 + c];
            X_s[r][c] = v;
        }
        __syncthreads();
#pragma unroll
        for (int k = 0; k < 32; k++) {
            float4 a = ((float4*)A_s[k])[tn];
#pragma unroll
            for (int m = 0; m < 8; m++) {
                float g = X_s[w * 8 + m][k];
                acc[m][0] += g * a.x;
                acc[m][1] += g * a.y;
                acc[m][2] += g * a.z;
                acc[m][3] += g * a.w;
            }
        }
    }
#pragma unroll
    for (int m = 0; m < 8; m++) {
        int row = row0 + w * 8 + m;
        if (row < n_nodes) {
            float4 v;
            v.x = acc[m][0] + b_s[tn * 4 + 0];
            v.y = acc[m][1] + b_s[tn * 4 + 1];
            v.z = acc[m][2] + b_s[tn * 4 + 2];
            v.w = acc[m][3] + b_s[tn * 4 + 3];
            ((float4*)(out + (long long)row * 128))[tn] = v;
        }
    }
}

// ---------------- fp16 mma edge-message kernel ----------------
// D(m=outcol 0..127, n=edge 0..127) = sum_k Ah[m][k] * G[e][k]
// K chunked by 32 halves (64B/row); per chunk: 2 x m16n8k16 per (am, bn).
// Smem rows padded to 20 words (80B).
template <int S>
__global__ __launch_bounds__(256, 2) void msg_mma(
    const void* __restrict__ ei, float* __restrict__ out, int n_edges, int rel) {
    __shared__ __align__(16) char s_raw[34048];   // 2x(128x20 words)=20.4KB; epi 64x132 f32=33.8KB
    __shared__ int s_src[128 * S];
    __shared__ int s_dst[128];
    __shared__ float s_inv[128];
    uint32_t* As = (uint32_t*)s_raw;              // [128 m][20 w]
    uint32_t* Gs = (uint32_t*)(s_raw + 10240);    // [128 e][20 w]
    float* stage = (float*)s_raw;                 // [64 e][132]

    const __half* xh = g_xh;
    const __half* Ah = (S == 1) ? g_Ah1 : (S == 2) ? g_Ah2 : g_Ah3;
    const int Ktot = S * 128;

    int t = threadIdx.x, l = t & 31, w = t >> 5;
    int wm = w & 3, wn = w >> 2;
    int e0 = blockIdx.x * 128;
    int m_count = n_edges - e0;
    if (m_count > 128) m_count = 128;
    int is64 = g_is64;

    // per-tile edge metadata
    for (int idx = t; idx < 128 * S; idx += 256) {
        int e = idx / S, k = idx - e * S;
        int src = 0;
        if (e < m_count) src = load_idx(ei, (long long)(e0 + e) * S + k, is64);
        s_src[idx] = src;
    }
    if (t < 128) {
        int dst = 0; float inv = 0.f;
        if (t < m_count) {
            dst = load_idx(ei, (long long)n_edges * S + (long long)(e0 + t) * S, is64);
            int dg = g_deg[rel * N_NODES + dst];
            inv = 1.0f / (float)(dg > 0 ? dg : 1);
        }
        s_dst[t] = dst; s_inv[t] = inv;
    }

    float c[2][8][4];
#pragma unroll
    for (int am = 0; am < 2; am++)
#pragma unroll
        for (int bn = 0; bn < 8; bn++)
#pragma unroll
            for (int j = 0; j < 4; j++) c[am][bn][j] = 0.f;

    const int NKC = 4 * S;            // 32-half chunks
    const int m0 = wm * 32, n0 = wn * 64;
    const int lr = l >> 2, lc = l & 3;
#pragma unroll 1
    for (int kc = 0; kc < NKC; kc++) {
        __syncthreads();
        int ks_slot = kc >> 2;        // source slot (128 k per slot = 4 chunks)
        // stage As + Gs: 128 rows x 16 words each, as uint4
#pragma unroll
        for (int i = 0; i < 2; i++) {
            int idx = t + 256 * i;
            int r = idx >> 2, qw = idx & 3;
            // A^T rows: 64B per chunk at byte offset r*Ktot*2 + kc*64
            uint4 av = *(const uint4*)((const char*)(Ah + (size_t)r * Ktot) + kc * 64 + qw * 16);
            *(uint4*)(As + r * 20 + qw * 4) = av;
            int src = s_src[r * S + ks_slot];
            uint4 gv = *(const uint4*)((const char*)(xh + (size_t)src * 128) + (kc & 3) * 64 + qw * 16);
            *(uint4*)(Gs + r * 20 + qw * 4) = gv;
        }
        __syncthreads();

#pragma unroll
        for (int j = 0; j < 2; j++) {             // two k16 groups per chunk
            uint2 aT[2], aB[2];
#pragma unroll
            for (int am = 0; am < 2; am++) {
                int mr = m0 + am * 16 + lr;
                aT[am] = *(uint2*)(As + mr * 20 + j * 8 + 2 * lc);
                aB[am] = *(uint2*)(As + (mr + 8) * 20 + j * 8 + 2 * lc);
            }
#pragma unroll
            for (int bn = 0; bn < 8; bn++) {
                int er = n0 + bn * 8 + lr;
                uint2 bv = *(uint2*)(Gs + er * 20 + j * 8 + 2 * lc);
#pragma unroll
                for (int am = 0; am < 2; am++)
                    mma_f16(c[am][bn], aT[am].x, aB[am].x, aT[am].y, aB[am].y,
                            bv.x, bv.y);
            }
        }
    }

    // epilogue: stage [64 e][128 m] halves in smem, vector-RED into out
#pragma unroll 1
    for (int h = 0; h < 2; h++) {
        __syncthreads();
        if (wn == h) {
#pragma unroll
            for (int am = 0; am < 2; am++)
#pragma unroll
                for (int bn = 0; bn < 8; bn++) {
                    int eloc = bn * 8 + 2 * lc;
                    int m = m0 + am * 16 + lr;
                    stage[eloc * 132 + m]           = c[am][bn][0];
                    stage[(eloc + 1) * 132 + m]     = c[am][bn][1];
                    stage[eloc * 132 + m + 8]       = c[am][bn][2];
                    stage[(eloc + 1) * 132 + m + 8] = c[am][bn][3];
                }
        }
        __syncthreads();
#pragma unroll 1
        for (int i = 0; i < 8; i++) {
            int idx = t + 256 * i;
            int eloc = idx >> 5, c4 = idx & 31;
            int e = h * 64 + eloc;
            if (e < m_count) {
                float inv = s_inv[e];
                float4 v = *(float4*)(stage + eloc * 132 + c4 * 4);
                float* p = out + (size_t)s_dst[e] * 128 + c4 * 4;
                red4(p, v.x * inv, v.y * inv, v.z * inv, v.w * inv);
            }
        }
    }
}

// ---------------- launch ----------------
extern "C" void kernel_launch(void* const* d_in, const int* in_sizes, int n_in,
                              void* d_out, int out_size) {
    const float *x = nullptr, *A1 = nullptr, *A2 = nullptr, *A3 = nullptr;
    const float *Cw = nullptr, *Cb = nullptr;
    const void *e1 = nullptr, *e2 = nullptr, *e3 = nullptr;

    for (int i = 0; i < n_in; i++) {
        int sz = in_sizes[i];
        if (sz == 12800000)      x = (const float*)d_in[i];
        else if (sz == 16384) {  if (!A1) A1 = (const float*)d_in[i]; else Cw = (const float*)d_in[i]; }
        else if (sz == 32768)    A2 = (const float*)d_in[i];
        else if (sz == 49152)    A3 = (const float*)d_in[i];
        else if (sz == 128)      Cb = (const float*)d_in[i];
        else if (sz == 800000)   e1 = d_in[i];
        else if (sz == 1200000){ if (!e2) e2 = d_in[i]; else e3 = d_in[i]; }
    }

    float* out = (float*)d_out;
    const int n1 = 400000, n2 = 300000, n3 = 200000;

    detect_kernel<<<1, 1>>>(e1);
    zero_deg_kernel<<<(3 * N_NODES + 255) / 256, 256>>>();
    deg_kernel<1><<<(n1 + 255) / 256, 256>>>(e1, n1, 0);
    deg_kernel<2><<<(n2 + 255) / 256, 256>>>(e2, n2, 1);
    deg_kernel<3><<<(n3 + 255) / 256, 256>>>(e3, n3, 2);

    conv_x_kernel<<<(N_NODES * 128 + 255) / 256, 256>>>(x);
    transpose_kernel<1><<<(128 * 128 + 255) / 256, 256>>>(A1);
    transpose_kernel<2><<<(128 * 256 + 255) / 256, 256>>>(A2);
    transpose_kernel<3><<<(128 * 384 + 255) / 256, 256>>>(A3);

    base_kernel<<<(N_NODES + 63) / 64, 256>>>(x, Cw, Cb, out, N_NODES);

    msg_mma<1><<<(n1 + 127) / 128, 256>>>(e1, out, n1, 0);
    msg_mma<2><<<(n2 + 127) / 128, 256>>>(e2, out, n2, 1);
    msg_mma<3><<<(n3 + 127) / 128, 256>>>(e3, out, n3, 2);
}

// round 9
// speedup vs baseline: 4.8220x; 1.4458x over previous
#include <cuda_runtime.h>
#include <cuda_fp16.h>
#include <cstdint>

#define N_NODES 100000

// ---------------- device scratch (no cudaMalloc allowed) ----------------
__device__ int    g_deg[3 * N_NODES];
__device__ int    g_is64;
__device__ __half g_xh[(size_t)N_NODES * 128];   // x -> fp16, word-permuted per k16 group
__device__ __half g_Ah1[128 * 128];              // A_r^T -> fp16, [n][k'] permuted
__device__ __half g_Ah2[128 * 256];
__device__ __half g_Ah3[128 * 384];
__device__ __half g_Ch[128 * 128];               // C_w^T -> fp16, permuted

// Half-index permutation inside each 16-half (k16) group:
// word w -> (w&3)*2 + (w>>2): lane's two fragment words adjacent -> one LDS.64.
__device__ __forceinline__ int hperm(int k) {     // k in [0,128)
    int w = k >> 1, g = w >> 3, wl = w & 7;
    int p = (wl & 3) * 2 + (wl >> 2);
    return g * 16 + p * 2 + (k & 1);
}

__device__ __forceinline__ uint32_t smem_u32(const void* p) {
    uint32_t a;
    asm("{ .reg .u64 t; cvta.to.shared.u64 t, %1; cvt.u32.u64 %0, t; }" : "=r"(a) : "l"(p));
    return a;
}
__device__ __forceinline__ void cp16(uint32_t dst, const void* src) {
    asm volatile("cp.async.cg.shared.global [%0], [%1], 16;" :: "r"(dst), "l"(src));
}
__device__ __forceinline__ void mma_f16(float* c, uint32_t a0, uint32_t a1,
                                        uint32_t a2, uint32_t a3,
                                        uint32_t b0, uint32_t b1) {
    asm volatile(
        "mma.sync.aligned.m16n8k16.row.col.f32.f16.f16.f32 "
        "{%0,%1,%2,%3}, {%4,%5,%6,%7}, {%8,%9}, {%0,%1,%2,%3};"
        : "+f"(c[0]), "+f"(c[1]), "+f"(c[2]), "+f"(c[3])
        : "r"(a0), "r"(a1), "r"(a2), "r"(a3), "r"(b0), "r"(b1));
}
__device__ __forceinline__ void red4(float* p, float x, float y, float z, float w) {
    asm volatile(
        "{ .reg .u64 g; cvta.to.global.u64 g, %0; "
        "red.global.add.v4.f32 [g], {%1,%2,%3,%4}; }"
        :: "l"(p), "f"(x), "f"(y), "f"(z), "f"(w) : "memory");
}
__device__ __forceinline__ int load_idx(const void* ei, long long pos, int is64) {
    int v = is64 ? (int)((const long long*)ei)[pos] : ((const int*)ei)[pos];
    return (v < 0) ? 0 : (v >= N_NODES ? N_NODES - 1 : v);
}

// ---------------- setup: zero deg + zero out + detect dtype ----------------
__global__ void setup_kernel(const void* e1, float* out, int out_n) {
    int tid = blockIdx.x * blockDim.x + threadIdx.x;
    int stride = gridDim.x * blockDim.x;
    for (int i = tid; i < 3 * N_NODES; i += stride) g_deg[i] = 0;
    float4 z = {0.f, 0.f, 0.f, 0.f};
    float4* o4 = (float4*)out;
    int n4 = out_n >> 2;
    for (int i = tid; i < n4; i += stride) o4[i] = z;
    if (tid == 0) {
        const long long* p = (const long long*)e1;
        int ok64 = 1;
        for (int i = 0; i < 128; i++) {
            long long v = p[i];
            if (v < 0 || v >= N_NODES) { ok64 = 0; break; }
        }
        g_is64 = ok64;
    }
}

// ---------------- all degree counts in one kernel ----------------
__global__ void deg_all_kernel(const void* __restrict__ e1, const void* __restrict__ e2,
                               const void* __restrict__ e3) {
    int i = blockIdx.x * blockDim.x + threadIdx.x;
    int is64 = g_is64;
    if (i < 400000) {
        int d = load_idx(e1, 400000LL + i, is64);
        atomicAdd(&g_deg[d], 1);
    } else if (i < 700000) {
        long long e = i - 400000;
        int d = load_idx(e2, 600000LL + e * 2, is64);
        atomicAdd(&g_deg[N_NODES + d], 1);
    } else if (i < 900000) {
        long long e = i - 700000;
        int d = load_idx(e3, 600000LL + e * 3, is64);
        atomicAdd(&g_deg[2 * N_NODES + d], 1);
    }
}

// ---------------- all fp16 conversions in one kernel ----------------
__device__ __forceinline__ void conv_mat(const float* A, __half* Ah, int Ktot, int idx) {
    int k = idx >> 7, n = idx & 127;                  // coalesced read of A[k][n]
    Ah[(size_t)n * Ktot + (k & ~127) + hperm(k & 127)] = __float2half_rn(A[idx]);
}
__global__ void conv_all_kernel(const float* __restrict__ x, const float* __restrict__ A1,
                                const float* __restrict__ A2, const float* __restrict__ A3,
                                const float* __restrict__ Cw) {
    const int NX = 6400000;                            // x as half2 pairs
    int tid = blockIdx.x * blockDim.x + threadIdx.x;
    int stride = gridDim.x * blockDim.x;
    const int TOT = NX + 16384 + 32768 + 49152 + 16384;
    for (int i = tid; i < TOT; i += stride) {
        if (i < NX) {
            int node = i >> 6, kl = (i & 63) * 2;
            float2 v = *(const float2*)(x + (size_t)node * 128 + kl);
            __half2 h = __floats2half2_rn(v.x, v.y);
            *(__half2*)(g_xh + (size_t)node * 128 + hperm(kl)) = h;
        } else if (i < NX + 16384)            conv_mat(A1, g_Ah1, 128, i - NX);
        else if (i < NX + 16384 + 32768)      conv_mat(A2, g_Ah2, 256, i - NX - 16384);
        else if (i < NX + 16384 + 32768 + 49152) conv_mat(A3, g_Ah3, 384, i - NX - 49152);
        else                                  conv_mat(Cw, g_Ch, 128, i - NX - 98304);
    }
}

// ---------------- fp16 mma edge-message kernel (cp.async pipelined) ----------------
// D(m=outcol, e=edge) = sum_k Ah[m][k] * xh[src(e,k)][k];  K chunked by 32 halves.
template <int S>
__global__ __launch_bounds__(256, 2) void msg_mma(
    const void* __restrict__ ei, float* __restrict__ out, int n_edges, int rel) {
    __shared__ __align__(16) char s_raw[40960];    // 2 buffers x (As 10240 + Gs 10240)
    __shared__ int s_src[128 * S];
    __shared__ int s_dst[128];
    __shared__ float s_inv[128];
    float* stage = (float*)s_raw;                  // epilogue alias [64 e][132]

    const __half* xh = g_xh;
    const __half* Ah = (S == 1) ? g_Ah1 : (S == 2) ? g_Ah2 : g_Ah3;
    const int Ktot = S * 128;

    int t = threadIdx.x, l = t & 31, w = t >> 5;
    int wm = w & 3, wn = w >> 2;
    int e0 = blockIdx.x * 128;
    int m_count = n_edges - e0;
    if (m_count > 128) m_count = 128;
    int is64 = g_is64;
    uint32_t sbase = smem_u32(s_raw);

    for (int idx = t; idx < 128 * S; idx += 256) {
        int e = idx / S, k = idx - e * S;
        int src = 0;
        if (e < m_count) src = load_idx(ei, (long long)(e0 + e) * S + k, is64);
        s_src[idx] = src;
    }
    if (t < 128) {
        int dst = 0; float inv = 0.f;
        if (t < m_count) {
            dst = load_idx(ei, (long long)n_edges * S + (long long)(e0 + t) * S, is64);
            int dg = g_deg[rel * N_NODES + dst];
            inv = 1.0f / (float)(dg > 0 ? dg : 1);
        }
        s_dst[t] = dst; s_inv[t] = inv;
    }
    __syncthreads();                                // s_src visible to stagers

    auto stage_chunk = [&](int kc, int p) {
        uint32_t As_b = sbase + p * 20480;
        uint32_t Gs_b = As_b + 10240;
        int ks_slot = kc >> 2;
#pragma unroll
        for (int i = 0; i < 2; i++) {
            int idx = t + 256 * i;
            int r = idx >> 2, qw = idx & 3;
            cp16(As_b + (r * 20 + qw * 4) * 4,
                 (const char*)(Ah + (size_t)r * Ktot) + kc * 64 + qw * 16);
            int src = s_src[r * S + ks_slot];
            cp16(Gs_b + (r * 20 + qw * 4) * 4,
                 (const char*)(xh + (size_t)src * 128) + (kc & 3) * 64 + qw * 16);
        }
        asm volatile("cp.async.commit_group;" ::: "memory");
    };

    float c[2][8][4];
#pragma unroll
    for (int am = 0; am < 2; am++)
#pragma unroll
        for (int bn = 0; bn < 8; bn++)
#pragma unroll
            for (int j = 0; j < 4; j++) c[am][bn][j] = 0.f;

    const int NKC = 4 * S;
    const int m0 = wm * 32, n0 = wn * 64;
    const int lr = l >> 2, lc = l & 3;
    stage_chunk(0, 0);
#pragma unroll 1
    for (int kc = 0; kc < NKC; kc++) {
        if (kc + 1 < NKC) {
            stage_chunk(kc + 1, (kc + 1) & 1);
            asm volatile("cp.async.wait_group 1;" ::: "memory");
        } else {
            asm volatile("cp.async.wait_group 0;" ::: "memory");
        }
        __syncthreads();
        uint32_t* As = (uint32_t*)(s_raw + (kc & 1) * 20480);
        uint32_t* Gs = (uint32_t*)(s_raw + (kc & 1) * 20480 + 10240);
#pragma unroll
        for (int j = 0; j < 2; j++) {              // two k16 groups per 32-half chunk
            uint2 aT[2], aB[2];
#pragma unroll
            for (int am = 0; am < 2; am++) {
                int mr = m0 + am * 16 + lr;
                aT[am] = *(uint2*)(As + mr * 20 + j * 8 + 2 * lc);
                aB[am] = *(uint2*)(As + (mr + 8) * 20 + j * 8 + 2 * lc);
            }
#pragma unroll
            for (int bn = 0; bn < 8; bn++) {
                int er = n0 + bn * 8 + lr;
                uint2 bv = *(uint2*)(Gs + er * 20 + j * 8 + 2 * lc);
#pragma unroll
                for (int am = 0; am < 2; am++)
                    mma_f16(c[am][bn], aT[am].x, aB[am].x, aT[am].y, aB[am].y,
                            bv.x, bv.y);
            }
        }
        __syncthreads();                            // reads done before rewrite
    }

    // epilogue: stage [64 e][128 m] halves, vector-RED into out
#pragma unroll 1
    for (int h = 0; h < 2; h++) {
        __syncthreads();
        if (wn == h) {
#pragma unroll
            for (int am = 0; am < 2; am++)
#pragma unroll
                for (int bn = 0; bn < 8; bn++) {
                    int eloc = bn * 8 + 2 * lc;
                    int m = m0 + am * 16 + lr;
                    stage[eloc * 132 + m]           = c[am][bn][0];
                    stage[(eloc + 1) * 132 + m]     = c[am][bn][1];
                    stage[eloc * 132 + m + 8]       = c[am][bn][2];
                    stage[(eloc + 1) * 132 + m + 8] = c[am][bn][3];
                }
        }
        __syncthreads();
#pragma unroll 1
        for (int i = 0; i < 8; i++) {
            int idx = t + 256 * i;
            int eloc = idx >> 5, c4 = idx & 31;
            int e = h * 64 + eloc;
            if (e < m_count) {
                float inv = s_inv[e];
                float4 v = *(float4*)(stage + eloc * 132 + c4 * 4);
                float* p = out + (size_t)s_dst[e] * 128 + c4 * 4;
                red4(p, v.x * inv, v.y * inv, v.z * inv, v.w * inv);
            }
        }
    }
}

// ---------------- fp16 mma base kernel: out += x@Cw + b (out pre-holds agg) ----------------
__global__ __launch_bounds__(256, 2) void base_mma(
    const float* __restrict__ Cb, float* __restrict__ out, int n_nodes) {
    __shared__ __align__(16) char s_raw[40960];
    __shared__ float b_s[128];
    float* stage = (float*)s_raw;

    const __half* xh = g_xh;
    const __half* Ah = g_Ch;

    int t = threadIdx.x, l = t & 31, w = t >> 5;
    int wm = w & 3, wn = w >> 2;
    int node0 = blockIdx.x * 128;
    int m_count = n_nodes - node0;
    if (m_count > 128) m_count = 128;
    uint32_t sbase = smem_u32(s_raw);
    if (t < 128) b_s[t] = Cb[t];
    __syncthreads();

    auto stage_chunk = [&](int kc, int p) {
        uint32_t As_b = sbase + p * 20480;
        uint32_t Gs_b = As_b + 10240;
#pragma unroll
        for (int i = 0; i < 2; i++) {
            int idx = t + 256 * i;
            int r = idx >> 2, qw = idx & 3;
            cp16(As_b + (r * 20 + qw * 4) * 4,
                 (const char*)(Ah + (size_t)r * 128) + kc * 64 + qw * 16);
            int node = node0 + r;
            if (node >= n_nodes) node = node0;
            cp16(Gs_b + (r * 20 + qw * 4) * 4,
                 (const char*)(xh + (size_t)node * 128) + kc * 64 + qw * 16);
        }
        asm volatile("cp.async.commit_group;" ::: "memory");
    };

    float c[2][8][4];
#pragma unroll
    for (int am = 0; am < 2; am++)
#pragma unroll
        for (int bn = 0; bn < 8; bn++)
#pragma unroll
            for (int j = 0; j < 4; j++) c[am][bn][j] = 0.f;

    const int m0 = wm * 32, n0 = wn * 64;
    const int lr = l >> 2, lc = l & 3;
    stage_chunk(0, 0);
#pragma unroll 1
    for (int kc = 0; kc < 4; kc++) {
        if (kc + 1 < 4) {
            stage_chunk(kc + 1, (kc + 1) & 1);
            asm volatile("cp.async.wait_group 1;" ::: "memory");
        } else {
            asm volatile("cp.async.wait_group 0;" ::: "memory");
        }
        __syncthreads();
        uint32_t* As = (uint32_t*)(s_raw + (kc & 1) * 20480);
        uint32_t* Gs = (uint32_t*)(s_raw + (kc & 1) * 20480 + 10240);
#pragma unroll
        for (int j = 0; j < 2; j++) {
            uint2 aT[2], aB[2];
#pragma unroll
            for (int am = 0; am < 2; am++) {
                int mr = m0 + am * 16 + lr;
                aT[am] = *(uint2*)(As + mr * 20 + j * 8 + 2 * lc);
                aB[am] = *(uint2*)(As + (mr + 8) * 20 + j * 8 + 2 * lc);
            }
#pragma unroll
            for (int bn = 0; bn < 8; bn++) {
                int er = n0 + bn * 8 + lr;
                uint2 bv = *(uint2*)(Gs + er * 20 + j * 8 + 2 * lc);
#pragma unroll
                for (int am = 0; am < 2; am++)
                    mma_f16(c[am][bn], aT[am].x, aB[am].x, aT[am].y, aB[am].y,
                            bv.x, bv.y);
            }
        }
        __syncthreads();
    }

#pragma unroll 1
    for (int h = 0; h < 2; h++) {
        __syncthreads();
        if (wn == h) {
#pragma unroll
            for (int am = 0; am < 2; am++)
#pragma unroll
                for (int bn = 0; bn < 8; bn++) {
                    int eloc = bn * 8 + 2 * lc;
                    int m = m0 + am * 16 + lr;
                    stage[eloc * 132 + m]           = c[am][bn][0];
                    stage[(eloc + 1) * 132 + m]     = c[am][bn][1];
                    stage[eloc * 132 + m + 8]       = c[am][bn][2];
                    stage[(eloc + 1) * 132 + m + 8] = c[am][bn][3];
                }
        }
        __syncthreads();
#pragma unroll 1
        for (int i = 0; i < 8; i++) {
            int idx = t + 256 * i;
            int eloc = idx >> 5, c4 = idx & 31;
            int node = node0 + h * 64 + eloc;
            if (node < n_nodes) {
                float4 v = *(float4*)(stage + eloc * 132 + c4 * 4);
                float4* p = (float4*)(out + (size_t)node * 128 + c4 * 4);
                float4 old = *p;
                float4 bb = *(float4*)(b_s + c4 * 4);
                v.x += old.x + bb.x; v.y += old.y + bb.y;
                v.z += old.z + bb.z; v.w += old.w + bb.w;
                *p = v;
            }
        }
    }
}

// ---------------- launch ----------------
extern "C" void kernel_launch(void* const* d_in, const int* in_sizes, int n_in,
                              void* d_out, int out_size) {
    const float *x = nullptr, *A1 = nullptr, *A2 = nullptr, *A3 = nullptr;
    const float *Cw = nullptr, *Cb = nullptr;
    const void *e1 = nullptr, *e2 = nullptr, *e3 = nullptr;

    for (int i = 0; i < n_in; i++) {
        int sz = in_sizes[i];
        if (sz == 12800000)      x = (const float*)d_in[i];
        else if (sz == 16384) {  if (!A1) A1 = (const float*)d_in[i]; else Cw = (const float*)d_in[i]; }
        else if (sz == 32768)    A2 = (const float*)d_in[i];
        else if (sz == 49152)    A3 = (const float*)d_in[i];
        else if (sz == 128)      Cb = (const float*)d_in[i];
        else if (sz == 800000)   e1 = d_in[i];
        else if (sz == 1200000){ if (!e2) e2 = d_in[i]; else e3 = d_in[i]; }
    }

    float* out = (float*)d_out;
    const int n1 = 400000, n2 = 300000, n3 = 200000;

    // 1: zero deg + zero out + detect dtype
    setup_kernel<<<6000, 256>>>(e1, out, 12800000);
    // 2: all in-degree counts
    deg_all_kernel<<<(900000 + 255) / 256, 256>>>(e1, e2, e3);
    // 3: all fp16 conversions (x, A1..A3, Cw)
    conv_all_kernel<<<6000, 256>>>(x, A1, A2, A3, Cw);
    // 4 (ncu capture slot): biggest msg kernel first
    msg_mma<2><<<(n2 + 127) / 128, 256>>>(e2, out, n2, 1);
    msg_mma<3><<<(n3 + 127) / 128, 256>>>(e3, out, n3, 2);
    msg_mma<1><<<(n1 + 127) / 128, 256>>>(e1, out, n1, 0);
    // 7: base adds x@Cw + b on top of the aggregated messages
    base_mma<<<(N_NODES + 127) / 128, 256>>>(Cb, out, N_NODES);
}